// round 8
// baseline (speedup 1.0000x reference)
#include <cuda_runtime.h>
#include <cuda_fp16.h>
#include <mma.h>
using namespace nvcuda;

#define NN 100000
#define NE 1600000
#define NG 64

// ---------------- scratch (device globals) ---------------------------------
__device__ float   g_dinv[NN];
__device__ int     g_deg[NN];
__device__ int     g_rowptr[NN];
__device__ int     g_cursor[NN];
__device__ int     g_bsum[128];
__device__ int     g_csr[NE];
__device__ __half2 g_h1p[(size_t)NN * 64];   // fp16: dinv * (x W1), 128 feat
__device__ float   g_h1 [(size_t)NN * 128];  // fp32: post agg+relu (gemm2 in)
__device__ __half2 g_h2p[(size_t)NN * 32];   // fp16: dinv * (h1 W2), 64 feat
__device__ float   g_gsum[NG * 64];
__device__ float   g_gcnt[NG];

__device__ __forceinline__ void red_add_v4(float* p, float4 v) {
    asm volatile("red.global.add.v4.f32 [%0], {%1, %2, %3, %4};"
                 :: "l"(p), "f"(v.x), "f"(v.y), "f"(v.z), "f"(v.w)
                 : "memory");
}

// ---------------- init ------------------------------------------------------
__global__ void k_init(int n) {
    int i = blockIdx.x * blockDim.x + threadIdx.x;
    if (i < n)       g_deg[i] = 0;
    if (i < NG * 64) g_gsum[i] = 0.0f;
    if (i < NG)      g_gcnt[i] = 0.0f;
}

// ---------------- degree histogram over dst --------------------------------
__global__ void k_hist(const int* __restrict__ dst, int E) {
    int e = blockIdx.x * blockDim.x + threadIdx.x;
    if (e < E) atomicAdd(&g_deg[dst[e]], 1);
}

// ---------------- scan step 1: per-block (1024) scan -----------------------
__global__ void k_scan1(int n) {
    __shared__ int sh[1024];
    int tid = threadIdx.x;
    int i = blockIdx.x * 1024 + tid;
    int v = (i < n) ? g_deg[i] : 0;
    sh[tid] = v;
    __syncthreads();
#pragma unroll
    for (int off = 1; off < 1024; off <<= 1) {
        int t = (tid >= off) ? sh[tid - off] : 0;
        __syncthreads();
        sh[tid] += t;
        __syncthreads();
    }
    if (i < n) g_rowptr[i] = sh[tid] - v;          // exclusive
    if (tid == 1023) g_bsum[blockIdx.x] = sh[1023];
}

// ---------------- scan step 2: warp-shuffle scan of block sums -------------
__global__ void k_scan2(int nb) {
    int lane = threadIdx.x;   // 32 threads
    int carry = 0;
    for (int base = 0; base < nb; base += 32) {
        int idx = base + lane;
        int orig = (idx < nb) ? g_bsum[idx] : 0;
        int v = orig;
#pragma unroll
        for (int off = 1; off < 32; off <<= 1) {
            int u = __shfl_up_sync(0xFFFFFFFFu, v, off);
            if (lane >= off) v += u;
        }
        if (idx < nb) g_bsum[idx] = v - orig + carry;   // exclusive + carry
        carry += __shfl_sync(0xFFFFFFFFu, v, 31);
    }
}

// ---------------- scan step 3: offsets, cursor, dinv, graph counts ---------
__global__ void k_scan3(const int* __restrict__ batch, int n) {
    int i = blockIdx.x * blockDim.x + threadIdx.x;
    if (i < n) {
        int r = g_rowptr[i] + g_bsum[i >> 10];
        g_rowptr[i] = r;
        g_cursor[i] = r;
        g_dinv[i]   = rsqrtf((float)g_deg[i] + 1.0f);   // +1 self loop
        atomicAdd(&g_gcnt[batch[i]], 1.0f);
    }
}

// ---------------- CSR scatter ----------------------------------------------
__global__ void k_scatter(const int* __restrict__ src,
                          const int* __restrict__ dst, int E) {
    int e = blockIdx.x * blockDim.x + threadIdx.x;
    if (e < E) {
        int pos = atomicAdd(&g_cursor[dst[e]], 1);
        g_csr[pos] = src[e];
    }
}

// ---------------- 3xTF32 GEMM: C[m] = fp16( (dinv[m]*A[m]) @ W ) -----------
// LAYER 1: A = x (arg), C = g_h1p, BN = 128.  LAYER 2: A = g_h1, C = g_h2p, BN = 64.
// 256 threads = 8 warps; block tile 128 x BN; warp tile 32 x BN/2.
template <int LAYER>
__global__ void k_gemm(const float* __restrict__ Ain,
                       const float* __restrict__ W, int M) {
    constexpr int BN  = (LAYER == 1) ? 128 : 64;
    constexpr int K   = 128;
    constexpr int KC  = 32;
    constexpr int LDA = KC + 8;
    constexpr int LDB = BN + 8;
    constexpr int LDS_ = 20;                    // stage stride: multiple of 4!
    constexpr int WN  = BN / 2;                 // warp tile N: 64 or 32
    constexpr int NF  = WN / 16;                // n-frags: 4 or 2
    const float* __restrict__ A = (LAYER == 1) ? Ain : g_h1;
    __half2* __restrict__     C = (LAYER == 1) ? g_h1p : g_h2p;
    constexpr int CH2 = BN / 2;                 // half2 per row

    __shared__ __align__(16) float As[128][LDA];
    __shared__ __align__(16) float Bs[KC][LDB];
    __shared__ __align__(16) float stage[8][16][LDS_];

    const int t    = threadIdx.x;
    const int wid  = t >> 5;
    const int lane = t & 31;
    const int mbase = blockIdx.x * 128;
    const int wm = (wid >> 1) * 32;             // warp row offset
    const int wn = (wid & 1) * WN;              // warp col offset

    wmma::fragment<wmma::accumulator, 16, 16, 8, float> c[2][NF];
#pragma unroll
    for (int i = 0; i < 2; i++)
#pragma unroll
        for (int j = 0; j < NF; j++) wmma::fill_fragment(c[i][j], 0.0f);

    for (int k0 = 0; k0 < K; k0 += KC) {
        // A tile: 128 x 32 floats, dinv-scaled rows; 1024 float4, 4/thread
#pragma unroll
        for (int j = 0; j < 4; j++) {
            int idx = t + j * 256;
            int row = idx >> 3;
            int kq  = (idx & 7) << 2;
            float4 av = make_float4(0.f, 0.f, 0.f, 0.f);
            float  s  = 0.0f;
            if (mbase + row < M) {
                av = *reinterpret_cast<const float4*>(
                    A + (size_t)(mbase + row) * K + k0 + kq);
                s = g_dinv[mbase + row];
            }
            As[row][kq + 0] = s * av.x;
            As[row][kq + 1] = s * av.y;
            As[row][kq + 2] = s * av.z;
            As[row][kq + 3] = s * av.w;
        }
        // B tile: KC x BN floats
        constexpr int B4   = KC * BN / 4;       // 1024 or 512
        constexpr int BIT  = B4 / 256;          // 4 or 2
#pragma unroll
        for (int j = 0; j < BIT; j++) {
            int idx = t + j * 256;
            int row = idx / (BN / 4);
            int col = (idx % (BN / 4)) << 2;
            float4 bv = *reinterpret_cast<const float4*>(
                W + (size_t)(k0 + row) * BN + col);
            Bs[row][col + 0] = bv.x;
            Bs[row][col + 1] = bv.y;
            Bs[row][col + 2] = bv.z;
            Bs[row][col + 3] = bv.w;
        }
        __syncthreads();

#pragma unroll
        for (int kk = 0; kk < KC; kk += 8) {
            wmma::fragment<wmma::matrix_a, 16, 16, 8, wmma::precision::tf32, wmma::row_major> ah[2], al[2];
            wmma::fragment<wmma::matrix_b, 16, 16, 8, wmma::precision::tf32, wmma::row_major> bh[NF], bl[NF];
#pragma unroll
            for (int i = 0; i < 2; i++) {
                wmma::load_matrix_sync(ah[i], &As[wm + i * 16][kk], LDA);
#pragma unroll
                for (int e = 0; e < ah[i].num_elements; e++) {
                    float v  = ah[i].x[e];
                    float hi = wmma::__float_to_tf32(v);
                    ah[i].x[e] = hi;
                    al[i].x[e] = wmma::__float_to_tf32(v - hi);
                }
            }
#pragma unroll
            for (int j = 0; j < NF; j++) {
                wmma::load_matrix_sync(bh[j], &Bs[kk][wn + j * 16], LDB);
#pragma unroll
                for (int e = 0; e < bh[j].num_elements; e++) {
                    float v  = bh[j].x[e];
                    float hi = wmma::__float_to_tf32(v);
                    bh[j].x[e] = hi;
                    bl[j].x[e] = wmma::__float_to_tf32(v - hi);
                }
            }
#pragma unroll
            for (int i = 0; i < 2; i++)
#pragma unroll
                for (int j = 0; j < NF; j++) {
                    wmma::mma_sync(c[i][j], al[i], bh[j], c[i][j]);
                    wmma::mma_sync(c[i][j], ah[i], bl[j], c[i][j]);
                    wmma::mma_sync(c[i][j], ah[i], bh[j], c[i][j]);
                }
        }
        __syncthreads();
    }

    // epilogue: stage through smem (ldm = 20, multiple of 4), convert to half2
#pragma unroll
    for (int i = 0; i < 2; i++)
#pragma unroll
        for (int j = 0; j < NF; j++) {
            wmma::store_matrix_sync(&stage[wid][0][0], c[i][j], LDS_,
                                    wmma::mem_row_major);
            __syncwarp();
#pragma unroll
            for (int it = 0; it < 4; it++) {
                int idx = lane + it * 32;            // 0..127
                int rr  = idx >> 3;                  // 0..15
                int cp  = idx & 7;                   // 0..7 (half2 col pair)
                int m = mbase + wm + i * 16 + rr;
                if (m < M) {
                    __half2 hv = __floats2half2_rn(stage[wid][rr][cp * 2],
                                                   stage[wid][rr][cp * 2 + 1]);
                    C[(size_t)m * CH2 + wn / 2 + j * 8 + cp] = hv;
                }
            }
            __syncwarp();
        }
}

// ---------------- agg layer 1 (D=128): warp per node, fp16 gather ----------
__global__ void k_agg1(const float* __restrict__ b1, int N) {
    int w = (blockIdx.x * blockDim.x + threadIdx.x) >> 5;
    if (w >= N) return;
    int lane = threadIdx.x & 31;
    const float2* H = (const float2*)g_h1p;   // 32 float2 (=4 halves each) per row

    int start = g_rowptr[w];
    int cnt   = g_deg[w];

    float2 raw = __ldg(H + (size_t)w * 32 + lane);    // self term
    float2 p0 = __half22float2(*reinterpret_cast<__half2*>(&raw.x));
    float2 p1 = __half22float2(*reinterpret_cast<__half2*>(&raw.y));
    float4 acc = make_float4(p0.x, p0.y, p1.x, p1.y);

    int j = 0;
    for (; j + 4 <= cnt; j += 4) {
        int s0 = __ldg(g_csr + start + j + 0);
        int s1 = __ldg(g_csr + start + j + 1);
        int s2 = __ldg(g_csr + start + j + 2);
        int s3 = __ldg(g_csr + start + j + 3);
        float2 r0 = __ldg(H + (size_t)s0 * 32 + lane);
        float2 r1 = __ldg(H + (size_t)s1 * 32 + lane);
        float2 r2 = __ldg(H + (size_t)s2 * 32 + lane);
        float2 r3 = __ldg(H + (size_t)s3 * 32 + lane);
        float2 a0 = __half22float2(*reinterpret_cast<__half2*>(&r0.x));
        float2 a1 = __half22float2(*reinterpret_cast<__half2*>(&r0.y));
        float2 b0 = __half22float2(*reinterpret_cast<__half2*>(&r1.x));
        float2 b1h = __half22float2(*reinterpret_cast<__half2*>(&r1.y));
        float2 c0 = __half22float2(*reinterpret_cast<__half2*>(&r2.x));
        float2 c1 = __half22float2(*reinterpret_cast<__half2*>(&r2.y));
        float2 d0 = __half22float2(*reinterpret_cast<__half2*>(&r3.x));
        float2 d1 = __half22float2(*reinterpret_cast<__half2*>(&r3.y));
        acc.x += a0.x + b0.x + c0.x + d0.x;
        acc.y += a0.y + b0.y + c0.y + d0.y;
        acc.z += a1.x + b1h.x + c1.x + d1.x;
        acc.w += a1.y + b1h.y + c1.y + d1.y;
    }
    for (; j < cnt; j++) {
        int s = __ldg(g_csr + start + j);
        float2 r = __ldg(H + (size_t)s * 32 + lane);
        float2 a0 = __half22float2(*reinterpret_cast<__half2*>(&r.x));
        float2 a1 = __half22float2(*reinterpret_cast<__half2*>(&r.y));
        acc.x += a0.x; acc.y += a0.y; acc.z += a1.x; acc.w += a1.y;
    }
    float di = g_dinv[w];
    float4 bb = __ldg((const float4*)b1 + lane);
    acc.x = fmaxf(di * acc.x + bb.x, 0.0f);
    acc.y = fmaxf(di * acc.y + bb.y, 0.0f);
    acc.z = fmaxf(di * acc.z + bb.z, 0.0f);
    acc.w = fmaxf(di * acc.w + bb.w, 0.0f);
    ((float4*)g_h1)[(size_t)w * 32 + lane] = acc;
}

// ---------------- agg layer 2 (D=64) + pool: 16 threads/node, fp16 gather --
__global__ void k_agg2(const int* __restrict__ batch,
                       const float* __restrict__ b2, int N) {
    int idx = blockIdx.x * blockDim.x + threadIdx.x;
    int node = idx >> 4;
    if (node >= N) return;
    int f4 = idx & 15;
    const float2* H = (const float2*)g_h2p;   // 16 float2 per row

    int start = g_rowptr[node];
    int cnt   = g_deg[node];

    float2 raw = __ldg(H + (size_t)node * 16 + f4);   // self term
    float2 p0 = __half22float2(*reinterpret_cast<__half2*>(&raw.x));
    float2 p1 = __half22float2(*reinterpret_cast<__half2*>(&raw.y));
    float4 acc = make_float4(p0.x, p0.y, p1.x, p1.y);

    int j = 0;
    for (; j + 4 <= cnt; j += 4) {
        int s0 = __ldg(g_csr + start + j + 0);
        int s1 = __ldg(g_csr + start + j + 1);
        int s2 = __ldg(g_csr + start + j + 2);
        int s3 = __ldg(g_csr + start + j + 3);
        float2 r0 = __ldg(H + (size_t)s0 * 16 + f4);
        float2 r1 = __ldg(H + (size_t)s1 * 16 + f4);
        float2 r2 = __ldg(H + (size_t)s2 * 16 + f4);
        float2 r3 = __ldg(H + (size_t)s3 * 16 + f4);
        float2 a0 = __half22float2(*reinterpret_cast<__half2*>(&r0.x));
        float2 a1 = __half22float2(*reinterpret_cast<__half2*>(&r0.y));
        float2 b0 = __half22float2(*reinterpret_cast<__half2*>(&r1.x));
        float2 b1h = __half22float2(*reinterpret_cast<__half2*>(&r1.y));
        float2 c0 = __half22float2(*reinterpret_cast<__half2*>(&r2.x));
        float2 c1 = __half22float2(*reinterpret_cast<__half2*>(&r2.y));
        float2 d0 = __half22float2(*reinterpret_cast<__half2*>(&r3.x));
        float2 d1 = __half22float2(*reinterpret_cast<__half2*>(&r3.y));
        acc.x += a0.x + b0.x + c0.x + d0.x;
        acc.y += a0.y + b0.y + c0.y + d0.y;
        acc.z += a1.x + b1h.x + c1.x + d1.x;
        acc.w += a1.y + b1h.y + c1.y + d1.y;
    }
    for (; j < cnt; j++) {
        int s = __ldg(g_csr + start + j);
        float2 r = __ldg(H + (size_t)s * 16 + f4);
        float2 a0 = __half22float2(*reinterpret_cast<__half2*>(&r.x));
        float2 a1 = __half22float2(*reinterpret_cast<__half2*>(&r.y));
        acc.x += a0.x; acc.y += a0.y; acc.z += a1.x; acc.w += a1.y;
    }
    float di = g_dinv[node];
    float4 bb = __ldg((const float4*)b2 + f4);
    acc.x = fmaxf(di * acc.x + bb.x, 0.0f);
    acc.y = fmaxf(di * acc.y + bb.y, 0.0f);
    acc.z = fmaxf(di * acc.z + bb.z, 0.0f);
    acc.w = fmaxf(di * acc.w + bb.w, 0.0f);

    int g = __ldg(batch + node);
    red_add_v4(&g_gsum[(g << 6) + (f4 << 2)], acc);
}

// ---------------- mean -----------------------------------------------------
__global__ void k_final(float* __restrict__ out) {
    int i = blockIdx.x * blockDim.x + threadIdx.x;
    if (i < NG * 64) out[i] = g_gsum[i] / fmaxf(g_gcnt[i >> 6], 1.0f);
}

// ===========================================================================
extern "C" void kernel_launch(void* const* d_in, const int* in_sizes, int n_in,
                              void* d_out, int out_size) {
    const float* x     = (const float*)d_in[0];
    const int*   ei    = (const int*)d_in[1];
    const int*   batch = (const int*)d_in[2];
    const float* W1    = (const float*)d_in[3];
    const float* b1    = (const float*)d_in[4];
    const float* W2    = (const float*)d_in[5];
    const float* b2    = (const float*)d_in[6];
    float*       out   = (float*)d_out;

    const int N = in_sizes[2];        // 100000
    const int E = in_sizes[1] / 2;    // 1600000
    const int* src = ei;
    const int* dst = ei + E;

    const int TB = 256;
    int nb_N  = (N + TB - 1) / TB;
    int nb_E  = (E + TB - 1) / TB;
    int nb_sc = (N + 1023) / 1024;    // scan blocks

    // graph prep: degree, rowptr, csr, dinv, graph counts
    k_init   <<<nb_N, TB>>>(N);
    k_hist   <<<nb_E, TB>>>(dst, E);
    k_scan1  <<<nb_sc, 1024>>>(N);
    k_scan2  <<<1, 32>>>(nb_sc);
    k_scan3  <<<nb_N, TB>>>(batch, N);
    k_scatter<<<nb_E, TB>>>(src, dst, E);

    // layer 1
    k_gemm<1><<<(N + 127) / 128, TB>>>(x, W1, N);
    k_agg1   <<<(N * 32 + TB - 1) / TB, TB>>>(b1, N);

    // layer 2 + pool
    k_gemm<2><<<(N + 127) / 128, TB>>>(nullptr, W2, N);
    k_agg2   <<<(N * 16 + TB - 1) / TB, TB>>>(batch, b2, N);

    k_final<<<(NG * 64 + TB - 1) / TB, TB>>>(out);
}